// round 16
// baseline (speedup 1.0000x reference)
#include <cuda_runtime.h>
#include <cuda_fp16.h>
#include <math.h>
#include <stdint.h>

#define BB   4
#define SS   1024
#define DD   1024
#define HH   16
#define DHD  64
#define LLAY 6
#define DFF  4096
#define MROWS (BB*SS)   // 4096

// ---------------- scratch (static device globals; no allocation) -----------
__device__ float g_x[MROWS*DD];
__device__ float g_tmp[MROWS*DD];
__device__ float g_out1[MROWS*DD];
__device__ __half g_xh[MROWS*DD];
__device__ __half g_o1h[MROWS*DD];
__device__ __half g_ctxh[MROWS*DD];
__device__ __half g_qkvh[(size_t)MROWS*3*DD];
__device__ __half g_hidh[(size_t)MROWS*DFF];

// transposed fp16 weights
__device__ __half g_wqkv[(size_t)LLAY*3*DD*DD];
__device__ __half g_wot[(size_t)LLAY*DD*DD];
__device__ __half g_w1t[(size_t)LLAY*DFF*DD];
__device__ __half g_w2t[(size_t)LLAY*DD*DFF];
__device__ float  g_bqkv[LLAY*3*DD];

// ---------------- helpers ---------------------------------------------------
__device__ __forceinline__ uint32_t smem_u32(const void* p){
    uint32_t a;
    asm("{ .reg .u64 t; cvta.to.shared.u64 t, %1; cvt.u32.u64 %0, t; }"
        : "=r"(a) : "l"(p));
    return a;
}
__device__ __forceinline__ void cp16(uint32_t dst, const void* src){
    asm volatile("cp.async.cg.shared.global [%0], [%1], 16;"
                 :: "r"(dst), "l"(src) : "memory");
}
#define CP_COMMIT() asm volatile("cp.async.commit_group;" ::: "memory")
#define CP_WAIT1()  asm volatile("cp.async.wait_group 1;" ::: "memory")
#define CP_WAIT0()  asm volatile("cp.async.wait_group 0;" ::: "memory")

#define MMA_F16(d, a, b) \
    asm volatile("mma.sync.aligned.m16n8k16.row.col.f32.f16.f16.f32 " \
        "{%0,%1,%2,%3}, {%4,%5,%6,%7}, {%8,%9}, {%0,%1,%2,%3};" \
        : "+f"((d)[0]),"+f"((d)[1]),"+f"((d)[2]),"+f"((d)[3]) \
        : "r"((a)[0]),"r"((a)[1]),"r"((a)[2]),"r"((a)[3]), \
          "r"((b)[0]),"r"((b)[1]))

#define LDSM4(r0, r1, r2, r3, addr) \
    asm volatile("ldmatrix.sync.aligned.m8n8.x4.shared.b16 {%0,%1,%2,%3}, [%4];" \
        : "=r"(r0), "=r"(r1), "=r"(r2), "=r"(r3) : "r"(addr))

#define LDSM4T(r0, r1, r2, r3, addr) \
    asm volatile("ldmatrix.sync.aligned.m8n8.x4.trans.shared.b16 {%0,%1,%2,%3}, [%4];" \
        : "=r"(r0), "=r"(r1), "=r"(r2), "=r"(r3) : "r"(addr))

__device__ __forceinline__ uint32_t packh2(float x, float y){
    __half2 h = __floats2half2_rn(x, y);
    return *(uint32_t*)&h;
}

// ---------------- weight transforms -----------------------------------------
__global__ void __launch_bounds__(256) trans_qkv_kernel(
    const float* __restrict__ Wq, const float* __restrict__ Wk,
    const float* __restrict__ Wv, __half* __restrict__ dst)
{
    __shared__ float t[32][33];
    int z = blockIdx.z;
    int l = z / 3, s = z % 3;
    const float* W = (s == 0 ? Wq : (s == 1 ? Wk : Wv)) + (size_t)l * DD * DD;
    int n0 = blockIdx.x << 5, k0 = blockIdx.y << 5;
    int tx = threadIdx.x, ty = threadIdx.y;
#pragma unroll
    for (int i = 0; i < 32; i += 8)
        t[ty + i][tx] = W[(size_t)(k0 + ty + i) * DD + n0 + tx];
    __syncthreads();
    __half* d = dst + (size_t)l * 3 * DD * DD + (size_t)s * DD * DD;
#pragma unroll
    for (int i = 0; i < 32; i += 8)
        d[(size_t)(n0 + ty + i) * DD + k0 + tx] = __float2half_rn(t[tx][ty + i]);
}

__global__ void __launch_bounds__(256) trans_wo_kernel(
    const float* __restrict__ Wo, __half* __restrict__ dst)
{
    __shared__ float t[32][33];
    int l = blockIdx.z;
    const float* W = Wo + (size_t)l * DD * DD;
    int n0 = blockIdx.x << 5, k0 = blockIdx.y << 5;
    int tx = threadIdx.x, ty = threadIdx.y;
#pragma unroll
    for (int i = 0; i < 32; i += 8)
        t[ty + i][tx] = W[(size_t)(k0 + ty + i) * DD + n0 + tx];
    __syncthreads();
    __half* d = dst + (size_t)l * DD * DD;
#pragma unroll
    for (int i = 0; i < 32; i += 8)
        d[(size_t)(n0 + ty + i) * DD + k0 + tx] = __float2half_rn(t[tx][ty + i]);
}

__global__ void __launch_bounds__(256) trans_w12_kernel(
    const float* __restrict__ W1, const float* __restrict__ W2,
    __half* __restrict__ d1, __half* __restrict__ d2)
{
    __shared__ float t[32][33];
    int z = blockIdx.z;
    int tx = threadIdx.x, ty = threadIdx.y;
    if (z < LLAY){
        int l = z;
        const float* W = W1 + (size_t)l * DD * DFF;
        int n0 = blockIdx.x << 5, k0 = blockIdx.y << 5;
#pragma unroll
        for (int i = 0; i < 32; i += 8)
            t[ty + i][tx] = W[(size_t)(k0 + ty + i) * DFF + n0 + tx];
        __syncthreads();
        __half* d = d1 + (size_t)l * DFF * DD;
#pragma unroll
        for (int i = 0; i < 32; i += 8)
            d[(size_t)(n0 + ty + i) * DD + k0 + tx] = __float2half_rn(t[tx][ty + i]);
    } else {
        int l = z - LLAY;
        const float* W = W2 + (size_t)l * DFF * DD;
        int n0 = blockIdx.y << 5, k0 = blockIdx.x << 5;
#pragma unroll
        for (int i = 0; i < 32; i += 8)
            t[ty + i][tx] = W[(size_t)(k0 + ty + i) * DD + n0 + tx];
        __syncthreads();
        __half* d = d2 + (size_t)l * DD * DFF;
#pragma unroll
        for (int i = 0; i < 32; i += 8)
            d[(size_t)(n0 + ty + i) * DFF + k0 + tx] = __float2half_rn(t[tx][ty + i]);
    }
}

__global__ void __launch_bounds__(256) bias_merge_kernel(
    const float* __restrict__ bq, const float* __restrict__ bk,
    const float* __restrict__ bv, float* __restrict__ dst)
{
    int idx = blockIdx.x * 256 + threadIdx.x;
    int l = idx / 3072, c = idx % 3072;
    int sec = c >> 10, cc = c & 1023;
    const float* s = sec == 0 ? bq : (sec == 1 ? bk : bv);
    dst[idx] = s[l * DD + cc];
}

// ---------------- FP16 dense GEMM (reg double-buffered fragments) -----------
// CTA 128x256, 512 threads, 16 warps (4x4), warp tile 32x64, KC=64, 2-stage.
#define KC     64
#define ROWB   144               // 64 fp16 = 128B + 16B pad (36 words)
#define ATILEB (128*ROWB)        // 18432
#define BTILEB (256*ROWB)        // 36864
#define STGB   (ATILEB+BTILEB)   // 55296
#define GSMEM  (2*STGB)          // 110592

template<bool RELU, bool WF32, bool WH>
__global__ void __launch_bounds__(512, 1) h_gemm(
    const __half* __restrict__ A, const __half* __restrict__ Bt,
    const float* __restrict__ bias,
    float* __restrict__ C, __half* __restrict__ Ch,
    int Ndim, int Kdim)
{
    extern __shared__ __align__(16) char smem[];
    int tid = threadIdx.x;
    int bm = blockIdx.y << 7, bn = blockIdx.x << 8;
    int NK = Kdim >> 6;
    uint32_t sbase = smem_u32(smem);

    int ar = tid >> 2, aq = tid & 3;
    int br = tid >> 1, bh2 = tid & 1;
    const char* gA = (const char*)(A + (size_t)(bm + ar) * Kdim) + aq * 32;
    const char* gB = (const char*)(Bt + (size_t)(bn + br) * Kdim) + bh2 * 64;
    uint32_t dA = (uint32_t)(ar * ROWB + aq * 32);
    uint32_t dB = (uint32_t)(ATILEB + br * ROWB + bh2 * 64);

#define ISSUE(slot, kt) do {                                        \
        uint32_t sd = sbase + (uint32_t)(slot) * STGB;              \
        size_t go = (size_t)(kt) * 128;                             \
        cp16(sd + dA,      gA + go); cp16(sd + dA + 16, gA + go + 16); \
        cp16(sd + dB,      gB + go); cp16(sd + dB + 16, gB + go + 16); \
        cp16(sd + dB + 32, gB + go + 32); cp16(sd + dB + 48, gB + go + 48); \
    } while(0)

    ISSUE(0, 0); CP_COMMIT();
    ISSUE(1, 1); CP_COMMIT();

    int wid = tid >> 5, lane = tid & 31;
    int wm = wid >> 2, wn = wid & 3;
    int grp = lane >> 2, qid = lane & 3;

    uint32_t aL = sbase +
        (uint32_t)((wm * 32 + (lane & 7) + ((lane >> 3) & 1) * 8) * ROWB
                   + (lane >> 4) * 16);
    uint32_t bL = sbase + ATILEB +
        (uint32_t)((wn * 64 + (lane & 7) + (lane >> 4) * 8) * ROWB
                   + ((lane >> 3) & 1) * 16);

    float acc[2][8][4];
#pragma unroll
    for (int i = 0; i < 2; i++)
#pragma unroll
        for (int j = 0; j < 8; j++)
#pragma unroll
            for (int r = 0; r < 4; r++) acc[i][j][r] = 0.f;

    uint32_t af[2][2][4], bf[2][8][2];

#define LOADFRAG(buf, stg, ks) do {                                        \
        _Pragma("unroll")                                                  \
        for (int i_ = 0; i_ < 2; i_++)                                     \
            LDSM4(af[buf][i_][0], af[buf][i_][1], af[buf][i_][2],          \
                  af[buf][i_][3],                                          \
                  aL + (stg) + (uint32_t)(i_ * 16 * ROWB) + (ks) * 32);    \
        _Pragma("unroll")                                                  \
        for (int p_ = 0; p_ < 4; p_++)                                     \
            LDSM4(bf[buf][2*p_][0], bf[buf][2*p_][1],                      \
                  bf[buf][2*p_+1][0], bf[buf][2*p_+1][1],                  \
                  bL + (stg) + (uint32_t)(p_ * 16 * ROWB) + (ks) * 32);    \
    } while(0)

    for (int kt = 0; kt < NK; kt++){
        CP_WAIT1();
        __syncthreads();
        uint32_t stg = (uint32_t)((kt & 1) * STGB);
        LOADFRAG(0, stg, 0);
#pragma unroll
        for (int ks = 0; ks < 4; ks++){
            int cur = ks & 1;
            if (ks < 3) LOADFRAG(cur ^ 1, stg, ks + 1);
#pragma unroll
            for (int i = 0; i < 2; i++)
#pragma unroll
                for (int j = 0; j < 8; j++)
                    MMA_F16(acc[i][j], af[cur][i], bf[cur][j]);
        }
        __syncthreads();
        if (kt + 2 < NK) ISSUE(kt & 1, kt + 2);
        CP_COMMIT();
    }
#undef LOADFRAG

#pragma unroll
    for (int i = 0; i < 2; i++){
        int row0 = bm + wm * 32 + i * 16 + grp;
#pragma unroll
        for (int j = 0; j < 8; j++){
            int col = bn + wn * 64 + j * 8 + qid * 2;
            float b0 = bias[col], b1 = bias[col + 1];
            float v00 = acc[i][j][0] + b0, v01 = acc[i][j][1] + b1;
            float v10 = acc[i][j][2] + b0, v11 = acc[i][j][3] + b1;
            if (RELU){
                v00 = fmaxf(v00, 0.f); v01 = fmaxf(v01, 0.f);
                v10 = fmaxf(v10, 0.f); v11 = fmaxf(v11, 0.f);
            }
            size_t o0 = (size_t)row0 * Ndim + col;
            size_t o1 = o0 + (size_t)8 * Ndim;
            if (WF32){
                float2 a2 = {v00, v01}, c2 = {v10, v11};
                *(float2*)(C + o0) = a2;
                *(float2*)(C + o1) = c2;
            }
            if (WH){
                *(uint32_t*)(Ch + o0) = packh2(v00, v01);
                *(uint32_t*)(Ch + o1) = packh2(v10, v11);
            }
        }
    }
#undef ISSUE
}

// ---------------- fused flash attention (fp16, ldmatrix, trans-V) -----------
#define QKPB   144
#define FQ_OFF 0
#define FK0    18432
#define FK1    36864
#define FV_OFF 55296
#define VPB_V  144
#define VPB2   272
#define FP_OFF 73728
#define PSLAB  4352
#define FM_OFF 108544
#define FL_SMEM 112640

__global__ void __launch_bounds__(256, 2) flash_attn(
    const __half* __restrict__ qkv,
    const float* __restrict__ mask, __half* __restrict__ Ch)
{
    extern __shared__ __align__(16) char smem[];
    uint32_t sb = smem_u32(smem);
    float* smf = (float*)smem;
    int tid = threadIdx.x;
    int bh = blockIdx.y, b = bh >> 4, h = bh & 15;
    int q0 = blockIdx.x << 7;

    int wid = tid >> 5, lane = tid & 31;
    int grp = lane >> 2, qid = lane & 3;

#pragma unroll
    for (int i = 0; i < 4; i++)
        smf[FM_OFF/4 + tid + i * 256] = mask[b * SS + tid + i * 256] * (-1e9f);

    int r = tid >> 1, hf = tid & 1;
    {
        const char* sq = (const char*)(qkv + (size_t)(b * SS + q0 + r) * 3072 + h * DHD) + hf * 64;
        const char* sk = (const char*)(qkv + (size_t)(b * SS + r) * 3072 + DD + h * DHD) + hf * 64;
        uint32_t dq = sb + FQ_OFF + r * QKPB + hf * 64;
        uint32_t dk = sb + FK0 + r * QKPB + hf * 64;
#pragma unroll
        for (int i = 0; i < 4; i++){
            cp16(dq + i * 16, sq + i * 16);
            cp16(dk + i * 16, sk + i * 16);
        }
    }
    CP_COMMIT(); CP_WAIT0();
    __syncthreads();

    float oacc[8][4];
#pragma unroll
    for (int j = 0; j < 8; j++)
#pragma unroll
        for (int c = 0; c < 4; c++) oacc[j][c] = 0.f;
    float m0 = -1e30f, m1 = -1e30f, l0 = 0.f, l1 = 0.f;

    uint32_t aQ = sb + FQ_OFF +
        (uint32_t)((wid * 16 + (lane & 7) + ((lane >> 3) & 1) * 8) * QKPB
                   + (lane >> 4) * 16);
    uint32_t bKoff =
        (uint32_t)(((lane & 7) + (lane >> 4) * 8) * QKPB
                   + ((lane >> 3) & 1) * 16);
    uint32_t aP = sb + FP_OFF +
        (uint32_t)(wid * PSLAB + ((lane & 7) + ((lane >> 3) & 1) * 8) * VPB2
                   + (lane >> 4) * 16);
    uint32_t bV = sb + FV_OFF +
        (uint32_t)(((lane & 7) + ((lane >> 3) & 1) * 8) * VPB_V
                   + (lane >> 4) * 16);

    uint32_t poff  = (uint32_t)(FP_OFF + wid * PSLAB + grp * VPB2 + qid * 4);

    for (int t = 0; t < 8; t++){
        __syncthreads();
        {
            const char* sv = (const char*)(qkv + (size_t)(b * SS + t * 128 + r) * 3072 + 2 * DD + h * DHD) + hf * 64;
            uint32_t dv = sb + FV_OFF + r * VPB_V + hf * 64;
#pragma unroll
            for (int i = 0; i < 4; i++)
                cp16(dv + i * 16, sv + i * 16);
        }
        CP_COMMIT();
        CP_WAIT1();
        __syncthreads();

        uint32_t kb = sb + ((t & 1) ? FK1 : FK0) + bKoff;
        float sacc[16][4];
#pragma unroll
        for (int j = 0; j < 16; j++)
#pragma unroll
            for (int c = 0; c < 4; c++) sacc[j][c] = 0.f;
#pragma unroll
        for (int ks = 0; ks < 4; ks++){
            uint32_t af[4];
            LDSM4(af[0], af[1], af[2], af[3], aQ + ks * 32);
#pragma unroll
            for (int p = 0; p < 8; p++){
                uint32_t bf0, bf1, bf2, bf3;
                LDSM4(bf0, bf1, bf2, bf3,
                      kb + (uint32_t)(p * 16 * QKPB) + ks * 32);
                uint32_t blo[2] = {bf0, bf1}, bhi[2] = {bf2, bf3};
                MMA_F16(sacc[2*p],     af, blo);
                MMA_F16(sacc[2*p + 1], af, bhi);
            }
        }
        CP_WAIT0();
        __syncthreads();

        float tm0 = -1e30f, tm1 = -1e30f;
#pragma unroll
        for (int j = 0; j < 16; j++){
            int col = t * 128 + j * 8 + 2 * qid;
            float mk0 = smf[FM_OFF/4 + col], mk1 = smf[FM_OFF/4 + col + 1];
            sacc[j][0] = sacc[j][0] * 0.125f + mk0;
            sacc[j][1] = sacc[j][1] * 0.125f + mk1;
            sacc[j][2] = sacc[j][2] * 0.125f + mk0;
            sacc[j][3] = sacc[j][3] * 0.125f + mk1;
            tm0 = fmaxf(tm0, fmaxf(sacc[j][0], sacc[j][1]));
            tm1 = fmaxf(tm1, fmaxf(sacc[j][2], sacc[j][3]));
        }
        tm0 = fmaxf(tm0, __shfl_xor_sync(~0u, tm0, 1));
        tm0 = fmaxf(tm0, __shfl_xor_sync(~0u, tm0, 2));
        tm1 = fmaxf(tm1, __shfl_xor_sync(~0u, tm1, 1));
        tm1 = fmaxf(tm1, __shfl_xor_sync(~0u, tm1, 2));
        float mn0 = fmaxf(m0, tm0), mn1 = fmaxf(m1, tm1);
        float f0 = __expf(m0 - mn0), f1 = __expf(m1 - mn1);
        float s0 = 0.f, s1 = 0.f;
#pragma unroll
        for (int j = 0; j < 16; j++){
            float p0 = __expf(sacc[j][0] - mn0);
            float p1 = __expf(sacc[j][1] - mn0);
            float p2 = __expf(sacc[j][2] - mn1);
            float p3 = __expf(sacc[j][3] - mn1);
            s0 += p0 + p1; s1 += p2 + p3;
            int colb = j * 16 + qid * 4;
            *(uint32_t*)(smem + poff - qid * 4 + colb) = packh2(p0, p1);
            *(uint32_t*)(smem + poff - qid * 4 + 8 * VPB2 + colb) = packh2(p2, p3);
        }
        s0 += __shfl_xor_sync(~0u, s0, 1); s0 += __shfl_xor_sync(~0u, s0, 2);
        s1 += __shfl_xor_sync(~0u, s1, 1); s1 += __shfl_xor_sync(~0u, s1, 2);
        l0 = l0 * f0 + s0; l1 = l1 * f1 + s1;
        m0 = mn0; m1 = mn1;
#pragma unroll
        for (int j = 0; j < 8; j++){
            oacc[j][0] *= f0; oacc[j][1] *= f0;
            oacc[j][2] *= f1; oacc[j][3] *= f1;
        }
        __syncwarp();

        if (t < 7){
            const char* sk = (const char*)(qkv + (size_t)(b * SS + (t + 1) * 128 + r) * 3072 + DD + h * DHD) + hf * 64;
            uint32_t dk = sb + ((t & 1) ? FK0 : FK1) + r * QKPB + hf * 64;
#pragma unroll
            for (int i = 0; i < 4; i++)
                cp16(dk + i * 16, sk + i * 16);
        }
        CP_COMMIT();

#pragma unroll
        for (int ks = 0; ks < 8; ks++){
            uint32_t af[4];
            LDSM4(af[0], af[1], af[2], af[3], aP + ks * 32);
#pragma unroll
            for (int p = 0; p < 4; p++){
                uint32_t bf0, bf1, bf2, bf3;
                LDSM4T(bf0, bf1, bf2, bf3,
                       bV + (uint32_t)(ks * 16 * VPB_V) + p * 32);
                uint32_t blo[2] = {bf0, bf1}, bhi[2] = {bf2, bf3};
                MMA_F16(oacc[2*p],     af, blo);
                MMA_F16(oacc[2*p + 1], af, bhi);
            }
        }
    }

    float inv0 = 1.f / l0, inv1 = 1.f / l1;
    int row0 = q0 + wid * 16 + grp;
#pragma unroll
    for (int j = 0; j < 8; j++){
        int col = j * 8 + 2 * qid;
        size_t o0 = (size_t)(b * SS + row0) * DD + h * DHD + col;
        size_t o1 = o0 + (size_t)8 * DD;
        *(uint32_t*)(Ch + o0) = packh2(oacc[j][0] * inv0, oacc[j][1] * inv0);
        *(uint32_t*)(Ch + o1) = packh2(oacc[j][2] * inv1, oacc[j][3] * inv1);
    }
}

// ---------------- embedding + positional encoding --------------------------
__global__ void __launch_bounds__(256) embed_kernel(
    const int* __restrict__ tokens, const float* __restrict__ emb,
    float* __restrict__ x, __half* __restrict__ xh)
{
    int idx = blockIdx.x * 256 + threadIdx.x;
    int m = idx >> 10;
    int d = idx & 1023;
    int s = m & (SS - 1);
    int tok = tokens[m];
    double i2  = (double)(2 * (d >> 1));
    double inv = exp(-i2 * (9.210340371976184 / 1024.0));
    double ang = (double)s * inv;
    float pe = (d & 1) ? (float)cos(ang) : (float)sin(ang);
    float v = emb[(size_t)tok * DD + d] + pe;
    x[idx] = v;
    xh[idx] = __float2half_rn(v);
}

// ---------------- fused residual + LayerNorm --------------------------------
__global__ void __launch_bounds__(256) ln_res_kernel(
    const float* __restrict__ X, const float* __restrict__ Y,
    const float* __restrict__ g, const float* __restrict__ beta,
    float* __restrict__ out, __half* __restrict__ outh)
{
    __shared__ float sh[8];
    size_t base = (size_t)blockIdx.x * DD;
    int tid = threadIdx.x;
    int c = tid << 2;
    float4 xv = *(const float4*)(X + base + c);
    float4 yv = *(const float4*)(Y + base + c);
    float v[4] = {xv.x + yv.x, xv.y + yv.y, xv.z + yv.z, xv.w + yv.w};
    float s = v[0] + v[1] + v[2] + v[3];
#pragma unroll
    for (int o = 16; o; o >>= 1) s += __shfl_xor_sync(~0u, s, o);
    if ((tid & 31) == 0) sh[tid >> 5] = s;
    __syncthreads();
    s = sh[tid & 7];
#pragma unroll
    for (int o = 4; o; o >>= 1) s += __shfl_xor_sync(~0u, s, o);
    float mean = s * (1.f / DD);

    float q = 0.f;
#pragma unroll
    for (int j = 0; j < 4; j++){ float d = v[j] - mean; q += d * d; }
#pragma unroll
    for (int o = 16; o; o >>= 1) q += __shfl_xor_sync(~0u, q, o);
    __syncthreads();
    if ((tid & 31) == 0) sh[tid >> 5] = q;
    __syncthreads();
    q = sh[tid & 7];
#pragma unroll
    for (int o = 4; o; o >>= 1) q += __shfl_xor_sync(~0u, q, o);
    float rstd = rsqrtf(q * (1.f / DD) + 1e-6f);

    float4 gv = *(const float4*)(g + c);
    float4 bv = *(const float4*)(beta + c);
    float o0 = (v[0] - mean) * rstd * gv.x + bv.x;
    float o1 = (v[1] - mean) * rstd * gv.y + bv.y;
    float o2 = (v[2] - mean) * rstd * gv.z + bv.z;
    float o3 = (v[3] - mean) * rstd * gv.w + bv.w;
    float4 ov = {o0, o1, o2, o3};
    *(float4*)(out + base + c) = ov;
    uint2 hv = {packh2(o0, o1), packh2(o2, o3)};
    *(uint2*)(outh + base + c) = hv;
}

// ---------------- host launcher --------------------------------------------
extern "C" void kernel_launch(void* const* d_in, const int* in_sizes, int n_in,
                              void* d_out, int out_size)
{
    const int*   tokens = (const int*)  d_in[0];
    const float* mask   = (const float*)d_in[1];
    const float* emb    = (const float*)d_in[2];
    const float* Wq = (const float*)d_in[3];
    const float* bq = (const float*)d_in[4];
    const float* Wk = (const float*)d_in[5];
    const float* bk = (const float*)d_in[6];
    const float* Wv = (const float*)d_in[7];
    const float* bv = (const float*)d_in[8];
    const float* Wo = (const float*)d_in[9];
    const float* bo = (const float*)d_in[10];
    const float* W1 = (const float*)d_in[11];
    const float* b1 = (const float*)d_in[12];
    const float* W2 = (const float*)d_in[13];
    const float* b2 = (const float*)d_in[14];
    const float* g1 = (const float*)d_in[15];
    const float* be1 = (const float*)d_in[16];
    const float* g2 = (const float*)d_in[17];
    const float* be2 = (const float*)d_in[18];
    float* out = (float*)d_out;

    float *x, *tmp, *out1, *bqkv;
    __half *xh, *o1h, *ctxh, *qkvh, *hidh, *wqkv, *wot, *w1t, *w2t;
    cudaGetSymbolAddress((void**)&x,    g_x);
    cudaGetSymbolAddress((void**)&tmp,  g_tmp);
    cudaGetSymbolAddress((void**)&out1, g_out1);
    cudaGetSymbolAddress((void**)&xh,   g_xh);
    cudaGetSymbolAddress((void**)&o1h,  g_o1h);
    cudaGetSymbolAddress((void**)&ctxh, g_ctxh);
    cudaGetSymbolAddress((void**)&qkvh, g_qkvh);
    cudaGetSymbolAddress((void**)&hidh, g_hidh);
    cudaGetSymbolAddress((void**)&wqkv, g_wqkv);
    cudaGetSymbolAddress((void**)&wot,  g_wot);
    cudaGetSymbolAddress((void**)&w1t,  g_w1t);
    cudaGetSymbolAddress((void**)&w2t,  g_w2t);
    cudaGetSymbolAddress((void**)&bqkv, g_bqkv);

    cudaFuncSetAttribute(h_gemm<false,false,true>,
                         cudaFuncAttributeMaxDynamicSharedMemorySize, GSMEM);
    cudaFuncSetAttribute(h_gemm<false,true,false>,
                         cudaFuncAttributeMaxDynamicSharedMemorySize, GSMEM);
    cudaFuncSetAttribute(h_gemm<true,false,true>,
                         cudaFuncAttributeMaxDynamicSharedMemorySize, GSMEM);
    cudaFuncSetAttribute(flash_attn,
                         cudaFuncAttributeMaxDynamicSharedMemorySize, FL_SMEM);

    dim3 tb(32, 8);
    dim3 gQKV(3*DD / 256, MROWS / 128);
    dim3 gDD (DD / 256,  MROWS / 128);
    dim3 gFF (DFF / 256, MROWS / 128);
    dim3 gFL (SS / 128, BB * HH);

    // launch order: QKV GEMM is the 4th kernel launch (ncu samples #4)
    trans_qkv_kernel<<<dim3(32, 32, 3*LLAY), tb>>>(Wq, Wk, Wv, wqkv);   // 1
    bias_merge_kernel<<<(LLAY*3*DD)/256, 256>>>(bq, bk, bv, bqkv);      // 2
    embed_kernel<<<(MROWS * DD) / 256, 256>>>(tokens, emb, x, xh);      // 3
    h_gemm<false,false,true><<<gQKV, 512, GSMEM>>>(                     // 4
        xh, wqkv, bqkv, 0, qkvh, 3*DD, DD);
    trans_wo_kernel<<<dim3(32, 32, LLAY), tb>>>(Wo, wot);               // 5
    trans_w12_kernel<<<dim3(128, 32, 2*LLAY), tb>>>(W1, W2, w1t, w2t);  // 6

    for (int i = 0; i < LLAY; i++){
        size_t woq = (size_t)i * 3 * DD * DD;
        size_t wo2 = (size_t)i * DD * DD;
        size_t f1 = (size_t)i * DFF * DD;
        size_t f2 = (size_t)i * DD * DFF;

        if (i > 0)
            h_gemm<false,false,true><<<gQKV, 512, GSMEM>>>(
                xh, wqkv + woq, bqkv + i*3*DD, 0, qkvh, 3*DD, DD);

        flash_attn<<<gFL, 256, FL_SMEM>>>(qkvh, mask, ctxh);

        h_gemm<false,true,false><<<gDD, 512, GSMEM>>>(
            ctxh, wot + wo2, bo + i*DD, tmp, 0, DD, DD);
        ln_res_kernel<<<MROWS, 256>>>(x, tmp, g1 + i*DD, be1 + i*DD,
                                      out1, o1h);

        h_gemm<true,false,true><<<gFF, 512, GSMEM>>>(
            o1h, w1t + f1, b1 + i*DFF, 0, hidh, DFF, DD);
        h_gemm<false,true,false><<<gDD, 512, GSMEM>>>(
            hidh, w2t + f2, b2 + i*DD, tmp, 0, DD, DFF);

        float* dst = (i == LLAY - 1) ? out : x;
        ln_res_kernel<<<MROWS, 256>>>(out1, tmp, g2 + i*DD, be2 + i*DD,
                                      dst, xh);
    }
}

// round 17
// speedup vs baseline: 1.7886x; 1.7886x over previous
#include <cuda_runtime.h>
#include <cuda_fp16.h>
#include <math.h>
#include <stdint.h>

#define BB   4
#define SS   1024
#define DD   1024
#define HH   16
#define DHD  64
#define LLAY 6
#define DFF  4096
#define MROWS (BB*SS)   // 4096

// ---------------- scratch (static device globals; no allocation) -----------
__device__ float g_x[MROWS*DD];
__device__ float g_tmp[MROWS*DD];
__device__ float g_out1[MROWS*DD];
__device__ __half g_xh[MROWS*DD];
__device__ __half g_o1h[MROWS*DD];
__device__ __half g_ctxh[MROWS*DD];
__device__ __half g_qkvh[(size_t)MROWS*3*DD];
__device__ __half g_hidh[(size_t)MROWS*DFF];

// transposed fp16 weights
__device__ __half g_wqkv[(size_t)LLAY*3*DD*DD];
__device__ __half g_wot[(size_t)LLAY*DD*DD];
__device__ __half g_w1t[(size_t)LLAY*DFF*DD];
__device__ __half g_w2t[(size_t)LLAY*DD*DFF];
__device__ float  g_bqkv[LLAY*3*DD];

// ---------------- helpers ---------------------------------------------------
__device__ __forceinline__ uint32_t smem_u32(const void* p){
    uint32_t a;
    asm("{ .reg .u64 t; cvta.to.shared.u64 t, %1; cvt.u32.u64 %0, t; }"
        : "=r"(a) : "l"(p));
    return a;
}
__device__ __forceinline__ void cp16(uint32_t dst, const void* src){
    asm volatile("cp.async.cg.shared.global [%0], [%1], 16;"
                 :: "r"(dst), "l"(src) : "memory");
}
#define CP_COMMIT() asm volatile("cp.async.commit_group;" ::: "memory")
#define CP_WAIT1()  asm volatile("cp.async.wait_group 1;" ::: "memory")
#define CP_WAIT0()  asm volatile("cp.async.wait_group 0;" ::: "memory")

#define MMA_F16(d, a, b) \
    asm volatile("mma.sync.aligned.m16n8k16.row.col.f32.f16.f16.f32 " \
        "{%0,%1,%2,%3}, {%4,%5,%6,%7}, {%8,%9}, {%0,%1,%2,%3};" \
        : "+f"((d)[0]),"+f"((d)[1]),"+f"((d)[2]),"+f"((d)[3]) \
        : "r"((a)[0]),"r"((a)[1]),"r"((a)[2]),"r"((a)[3]), \
          "r"((b)[0]),"r"((b)[1]))

#define LDSM4(r0, r1, r2, r3, addr) \
    asm volatile("ldmatrix.sync.aligned.m8n8.x4.shared.b16 {%0,%1,%2,%3}, [%4];" \
        : "=r"(r0), "=r"(r1), "=r"(r2), "=r"(r3) : "r"(addr))

#define LDSM4T(r0, r1, r2, r3, addr) \
    asm volatile("ldmatrix.sync.aligned.m8n8.x4.trans.shared.b16 {%0,%1,%2,%3}, [%4];" \
        : "=r"(r0), "=r"(r1), "=r"(r2), "=r"(r3) : "r"(addr))

__device__ __forceinline__ uint32_t packh2(float x, float y){
    __half2 h = __floats2half2_rn(x, y);
    return *(uint32_t*)&h;
}

// ---------------- weight transforms -----------------------------------------
__global__ void __launch_bounds__(256) trans_qkv_kernel(
    const float* __restrict__ Wq, const float* __restrict__ Wk,
    const float* __restrict__ Wv, __half* __restrict__ dst)
{
    __shared__ float t[32][33];
    int z = blockIdx.z;
    int l = z / 3, s = z % 3;
    const float* W = (s == 0 ? Wq : (s == 1 ? Wk : Wv)) + (size_t)l * DD * DD;
    int n0 = blockIdx.x << 5, k0 = blockIdx.y << 5;
    int tx = threadIdx.x, ty = threadIdx.y;
#pragma unroll
    for (int i = 0; i < 32; i += 8)
        t[ty + i][tx] = W[(size_t)(k0 + ty + i) * DD + n0 + tx];
    __syncthreads();
    __half* d = dst + (size_t)l * 3 * DD * DD + (size_t)s * DD * DD;
#pragma unroll
    for (int i = 0; i < 32; i += 8)
        d[(size_t)(n0 + ty + i) * DD + k0 + tx] = __float2half_rn(t[tx][ty + i]);
}

__global__ void __launch_bounds__(256) trans_wo_kernel(
    const float* __restrict__ Wo, __half* __restrict__ dst)
{
    __shared__ float t[32][33];
    int l = blockIdx.z;
    const float* W = Wo + (size_t)l * DD * DD;
    int n0 = blockIdx.x << 5, k0 = blockIdx.y << 5;
    int tx = threadIdx.x, ty = threadIdx.y;
#pragma unroll
    for (int i = 0; i < 32; i += 8)
        t[ty + i][tx] = W[(size_t)(k0 + ty + i) * DD + n0 + tx];
    __syncthreads();
    __half* d = dst + (size_t)l * DD * DD;
#pragma unroll
    for (int i = 0; i < 32; i += 8)
        d[(size_t)(n0 + ty + i) * DD + k0 + tx] = __float2half_rn(t[tx][ty + i]);
}

__global__ void __launch_bounds__(256) trans_w12_kernel(
    const float* __restrict__ W1, const float* __restrict__ W2,
    __half* __restrict__ d1, __half* __restrict__ d2)
{
    __shared__ float t[32][33];
    int z = blockIdx.z;
    int tx = threadIdx.x, ty = threadIdx.y;
    if (z < LLAY){
        int l = z;
        const float* W = W1 + (size_t)l * DD * DFF;
        int n0 = blockIdx.x << 5, k0 = blockIdx.y << 5;
#pragma unroll
        for (int i = 0; i < 32; i += 8)
            t[ty + i][tx] = W[(size_t)(k0 + ty + i) * DFF + n0 + tx];
        __syncthreads();
        __half* d = d1 + (size_t)l * DFF * DD;
#pragma unroll
        for (int i = 0; i < 32; i += 8)
            d[(size_t)(n0 + ty + i) * DD + k0 + tx] = __float2half_rn(t[tx][ty + i]);
    } else {
        int l = z - LLAY;
        const float* W = W2 + (size_t)l * DFF * DD;
        int n0 = blockIdx.y << 5, k0 = blockIdx.x << 5;
#pragma unroll
        for (int i = 0; i < 32; i += 8)
            t[ty + i][tx] = W[(size_t)(k0 + ty + i) * DD + n0 + tx];
        __syncthreads();
        __half* d = d2 + (size_t)l * DD * DFF;
#pragma unroll
        for (int i = 0; i < 32; i += 8)
            d[(size_t)(n0 + ty + i) * DFF + k0 + tx] = __float2half_rn(t[tx][ty + i]);
    }
}

__global__ void __launch_bounds__(256) bias_merge_kernel(
    const float* __restrict__ bq, const float* __restrict__ bk,
    const float* __restrict__ bv, float* __restrict__ dst)
{
    int idx = blockIdx.x * 256 + threadIdx.x;
    int l = idx / 3072, c = idx % 3072;
    int sec = c >> 10, cc = c & 1023;
    const float* s = sec == 0 ? bq : (sec == 1 ? bk : bv);
    dst[idx] = s[l * DD + cc];
}

// ---------------- FP16 dense GEMM (R15/R11 proven config) -------------------
// CTA 128x256, 512 threads, 16 warps (4x4), warp tile 32x64, KC=64, 2-stage.
#define KC     64
#define ROWB   144               // 64 fp16 = 128B + 16B pad (36 words)
#define ATILEB (128*ROWB)        // 18432
#define BTILEB (256*ROWB)        // 36864
#define STGB   (ATILEB+BTILEB)   // 55296
#define GSMEM  (2*STGB)          // 110592

template<bool RELU, bool WF32, bool WH>
__global__ void __launch_bounds__(512, 1) h_gemm(
    const __half* __restrict__ A, const __half* __restrict__ Bt,
    const float* __restrict__ bias,
    float* __restrict__ C, __half* __restrict__ Ch,
    int Ndim, int Kdim)
{
    extern __shared__ __align__(16) char smem[];
    int tid = threadIdx.x;
    int bm = blockIdx.y << 7, bn = blockIdx.x << 8;
    int NK = Kdim >> 6;
    uint32_t sbase = smem_u32(smem);

    int ar = tid >> 2, aq = tid & 3;
    int br = tid >> 1, bh2 = tid & 1;
    const char* gA = (const char*)(A + (size_t)(bm + ar) * Kdim) + aq * 32;
    const char* gB = (const char*)(Bt + (size_t)(bn + br) * Kdim) + bh2 * 64;
    uint32_t dA = (uint32_t)(ar * ROWB + aq * 32);
    uint32_t dB = (uint32_t)(ATILEB + br * ROWB + bh2 * 64);

#define ISSUE(slot, kt) do {                                        \
        uint32_t sd = sbase + (uint32_t)(slot) * STGB;              \
        size_t go = (size_t)(kt) * 128;                             \
        cp16(sd + dA,      gA + go); cp16(sd + dA + 16, gA + go + 16); \
        cp16(sd + dB,      gB + go); cp16(sd + dB + 16, gB + go + 16); \
        cp16(sd + dB + 32, gB + go + 32); cp16(sd + dB + 48, gB + go + 48); \
    } while(0)

    ISSUE(0, 0); CP_COMMIT();
    ISSUE(1, 1); CP_COMMIT();

    int wid = tid >> 5, lane = tid & 31;
    int wm = wid >> 2, wn = wid & 3;
    int grp = lane >> 2, qid = lane & 3;

    uint32_t aL = sbase +
        (uint32_t)((wm * 32 + (lane & 7) + ((lane >> 3) & 1) * 8) * ROWB
                   + (lane >> 4) * 16);
    uint32_t bL = sbase + ATILEB +
        (uint32_t)((wn * 64 + (lane & 7) + (lane >> 4) * 8) * ROWB
                   + ((lane >> 3) & 1) * 16);

    float acc[2][8][4];
#pragma unroll
    for (int i = 0; i < 2; i++)
#pragma unroll
        for (int j = 0; j < 8; j++)
#pragma unroll
            for (int r = 0; r < 4; r++) acc[i][j][r] = 0.f;

    for (int kt = 0; kt < NK; kt++){
        CP_WAIT1();
        __syncthreads();
        uint32_t stg = (uint32_t)((kt & 1) * STGB);
#pragma unroll
        for (int ks = 0; ks < 4; ks++){
            uint32_t af[2][4], bf[8][2];
#pragma unroll
            for (int i = 0; i < 2; i++)
                LDSM4(af[i][0], af[i][1], af[i][2], af[i][3],
                      aL + stg + (uint32_t)(i * 16 * ROWB) + ks * 32);
#pragma unroll
            for (int p = 0; p < 4; p++)
                LDSM4(bf[2*p][0], bf[2*p][1], bf[2*p+1][0], bf[2*p+1][1],
                      bL + stg + (uint32_t)(p * 16 * ROWB) + ks * 32);
#pragma unroll
            for (int i = 0; i < 2; i++)
#pragma unroll
                for (int j = 0; j < 8; j++)
                    MMA_F16(acc[i][j], af[i], bf[j]);
        }
        __syncthreads();
        if (kt + 2 < NK) ISSUE(kt & 1, kt + 2);
        CP_COMMIT();
    }

#pragma unroll
    for (int i = 0; i < 2; i++){
        int row0 = bm + wm * 32 + i * 16 + grp;
#pragma unroll
        for (int j = 0; j < 8; j++){
            int col = bn + wn * 64 + j * 8 + qid * 2;
            float b0 = bias[col], b1 = bias[col + 1];
            float v00 = acc[i][j][0] + b0, v01 = acc[i][j][1] + b1;
            float v10 = acc[i][j][2] + b0, v11 = acc[i][j][3] + b1;
            if (RELU){
                v00 = fmaxf(v00, 0.f); v01 = fmaxf(v01, 0.f);
                v10 = fmaxf(v10, 0.f); v11 = fmaxf(v11, 0.f);
            }
            size_t o0 = (size_t)row0 * Ndim + col;
            size_t o1 = o0 + (size_t)8 * Ndim;
            if (WF32){
                float2 a2 = {v00, v01}, c2 = {v10, v11};
                *(float2*)(C + o0) = a2;
                *(float2*)(C + o1) = c2;
            }
            if (WH){
                *(uint32_t*)(Ch + o0) = packh2(v00, v01);
                *(uint32_t*)(Ch + o1) = packh2(v10, v11);
            }
        }
    }
#undef ISSUE
}

// ---------------- fused flash attention (fp16, ldmatrix, trans-V) -----------
#define QKPB   144
#define FQ_OFF 0
#define FK0    18432
#define FK1    36864
#define FV_OFF 55296
#define VPB_V  144
#define VPB2   272
#define FP_OFF 73728
#define PSLAB  4352
#define FM_OFF 108544
#define FL_SMEM 112640

__global__ void __launch_bounds__(256, 2) flash_attn(
    const __half* __restrict__ qkv,
    const float* __restrict__ mask, __half* __restrict__ Ch)
{
    extern __shared__ __align__(16) char smem[];
    uint32_t sb = smem_u32(smem);
    float* smf = (float*)smem;
    int tid = threadIdx.x;
    int bh = blockIdx.y, b = bh >> 4, h = bh & 15;
    int q0 = blockIdx.x << 7;

    int wid = tid >> 5, lane = tid & 31;
    int grp = lane >> 2, qid = lane & 3;

#pragma unroll
    for (int i = 0; i < 4; i++)
        smf[FM_OFF/4 + tid + i * 256] = mask[b * SS + tid + i * 256] * (-1e9f);

    int r = tid >> 1, hf = tid & 1;
    {
        const char* sq = (const char*)(qkv + (size_t)(b * SS + q0 + r) * 3072 + h * DHD) + hf * 64;
        const char* sk = (const char*)(qkv + (size_t)(b * SS + r) * 3072 + DD + h * DHD) + hf * 64;
        uint32_t dq = sb + FQ_OFF + r * QKPB + hf * 64;
        uint32_t dk = sb + FK0 + r * QKPB + hf * 64;
#pragma unroll
        for (int i = 0; i < 4; i++){
            cp16(dq + i * 16, sq + i * 16);
            cp16(dk + i * 16, sk + i * 16);
        }
    }
    CP_COMMIT(); CP_WAIT0();
    __syncthreads();

    float oacc[8][4];
#pragma unroll
    for (int j = 0; j < 8; j++)
#pragma unroll
        for (int c = 0; c < 4; c++) oacc[j][c] = 0.f;
    float m0 = -1e30f, m1 = -1e30f, l0 = 0.f, l1 = 0.f;

    uint32_t aQ = sb + FQ_OFF +
        (uint32_t)((wid * 16 + (lane & 7) + ((lane >> 3) & 1) * 8) * QKPB
                   + (lane >> 4) * 16);
    uint32_t bKoff =
        (uint32_t)(((lane & 7) + (lane >> 4) * 8) * QKPB
                   + ((lane >> 3) & 1) * 16);
    uint32_t aP = sb + FP_OFF +
        (uint32_t)(wid * PSLAB + ((lane & 7) + ((lane >> 3) & 1) * 8) * VPB2
                   + (lane >> 4) * 16);
    uint32_t bV = sb + FV_OFF +
        (uint32_t)(((lane & 7) + ((lane >> 3) & 1) * 8) * VPB_V
                   + (lane >> 4) * 16);

    uint32_t poff  = (uint32_t)(FP_OFF + wid * PSLAB + grp * VPB2 + qid * 4);

    for (int t = 0; t < 8; t++){
        __syncthreads();
        {
            const char* sv = (const char*)(qkv + (size_t)(b * SS + t * 128 + r) * 3072 + 2 * DD + h * DHD) + hf * 64;
            uint32_t dv = sb + FV_OFF + r * VPB_V + hf * 64;
#pragma unroll
            for (int i = 0; i < 4; i++)
                cp16(dv + i * 16, sv + i * 16);
        }
        CP_COMMIT();
        CP_WAIT1();
        __syncthreads();

        uint32_t kb = sb + ((t & 1) ? FK1 : FK0) + bKoff;
        float sacc[16][4];
#pragma unroll
        for (int j = 0; j < 16; j++)
#pragma unroll
            for (int c = 0; c < 4; c++) sacc[j][c] = 0.f;
#pragma unroll
        for (int ks = 0; ks < 4; ks++){
            uint32_t af[4];
            LDSM4(af[0], af[1], af[2], af[3], aQ + ks * 32);
#pragma unroll
            for (int p = 0; p < 8; p++){
                uint32_t bf0, bf1, bf2, bf3;
                LDSM4(bf0, bf1, bf2, bf3,
                      kb + (uint32_t)(p * 16 * QKPB) + ks * 32);
                uint32_t blo[2] = {bf0, bf1}, bhi[2] = {bf2, bf3};
                MMA_F16(sacc[2*p],     af, blo);
                MMA_F16(sacc[2*p + 1], af, bhi);
            }
        }
        CP_WAIT0();
        __syncthreads();

        float tm0 = -1e30f, tm1 = -1e30f;
#pragma unroll
        for (int j = 0; j < 16; j++){
            int col = t * 128 + j * 8 + 2 * qid;
            float mk0 = smf[FM_OFF/4 + col], mk1 = smf[FM_OFF/4 + col + 1];
            sacc[j][0] = sacc[j][0] * 0.125f + mk0;
            sacc[j][1] = sacc[j][1] * 0.125f + mk1;
            sacc[j][2] = sacc[j][2] * 0.125f + mk0;
            sacc[j][3] = sacc[j][3] * 0.125f + mk1;
            tm0 = fmaxf(tm0, fmaxf(sacc[j][0], sacc[j][1]));
            tm1 = fmaxf(tm1, fmaxf(sacc[j][2], sacc[j][3]));
        }
        tm0 = fmaxf(tm0, __shfl_xor_sync(~0u, tm0, 1));
        tm0 = fmaxf(tm0, __shfl_xor_sync(~0u, tm0, 2));
        tm1 = fmaxf(tm1, __shfl_xor_sync(~0u, tm1, 1));
        tm1 = fmaxf(tm1, __shfl_xor_sync(~0u, tm1, 2));
        float mn0 = fmaxf(m0, tm0), mn1 = fmaxf(m1, tm1);
        float f0 = __expf(m0 - mn0), f1 = __expf(m1 - mn1);
        float s0 = 0.f, s1 = 0.f;
#pragma unroll
        for (int j = 0; j < 16; j++){
            float p0 = __expf(sacc[j][0] - mn0);
            float p1 = __expf(sacc[j][1] - mn0);
            float p2 = __expf(sacc[j][2] - mn1);
            float p3 = __expf(sacc[j][3] - mn1);
            s0 += p0 + p1; s1 += p2 + p3;
            int colb = j * 16 + qid * 4;
            *(uint32_t*)(smem + poff - qid * 4 + colb) = packh2(p0, p1);
            *(uint32_t*)(smem + poff - qid * 4 + 8 * VPB2 + colb) = packh2(p2, p3);
        }
        s0 += __shfl_xor_sync(~0u, s0, 1); s0 += __shfl_xor_sync(~0u, s0, 2);
        s1 += __shfl_xor_sync(~0u, s1, 1); s1 += __shfl_xor_sync(~0u, s1, 2);
        l0 = l0 * f0 + s0; l1 = l1 * f1 + s1;
        m0 = mn0; m1 = mn1;
#pragma unroll
        for (int j = 0; j < 8; j++){
            oacc[j][0] *= f0; oacc[j][1] *= f0;
            oacc[j][2] *= f1; oacc[j][3] *= f1;
        }
        __syncwarp();

        if (t < 7){
            const char* sk = (const char*)(qkv + (size_t)(b * SS + (t + 1) * 128 + r) * 3072 + DD + h * DHD) + hf * 64;
            uint32_t dk = sb + ((t & 1) ? FK0 : FK1) + r * QKPB + hf * 64;
#pragma unroll
            for (int i = 0; i < 4; i++)
                cp16(dk + i * 16, sk + i * 16);
        }
        CP_COMMIT();

#pragma unroll
        for (int ks = 0; ks < 8; ks++){
            uint32_t af[4];
            LDSM4(af[0], af[1], af[2], af[3], aP + ks * 32);
#pragma unroll
            for (int p = 0; p < 4; p++){
                uint32_t bf0, bf1, bf2, bf3;
                LDSM4T(bf0, bf1, bf2, bf3,
                       bV + (uint32_t)(ks * 16 * VPB_V) + p * 32);
                uint32_t blo[2] = {bf0, bf1}, bhi[2] = {bf2, bf3};
                MMA_F16(oacc[2*p],     af, blo);
                MMA_F16(oacc[2*p + 1], af, bhi);
            }
        }
    }

    float inv0 = 1.f / l0, inv1 = 1.f / l1;
    int row0 = q0 + wid * 16 + grp;
#pragma unroll
    for (int j = 0; j < 8; j++){
        int col = j * 8 + 2 * qid;
        size_t o0 = (size_t)(b * SS + row0) * DD + h * DHD + col;
        size_t o1 = o0 + (size_t)8 * DD;
        *(uint32_t*)(Ch + o0) = packh2(oacc[j][0] * inv0, oacc[j][1] * inv0);
        *(uint32_t*)(Ch + o1) = packh2(oacc[j][2] * inv1, oacc[j][3] * inv1);
    }
}

// ---------------- embedding + positional encoding (fp32 trig) ---------------
__global__ void __launch_bounds__(256) embed_kernel(
    const int* __restrict__ tokens, const float* __restrict__ emb,
    float* __restrict__ x, __half* __restrict__ xh)
{
    int idx = blockIdx.x * 256 + threadIdx.x;
    int m = idx >> 10;
    int d = idx & 1023;
    int s = m & (SS - 1);
    int tok = tokens[m];
    float i2  = (float)(2 * (d >> 1));
    float inv = expf(-i2 * (9.210340371976184f / 1024.0f));
    float ang = (float)s * inv;
    float pe = (d & 1) ? cosf(ang) : sinf(ang);
    float v = emb[(size_t)tok * DD + d] + pe;
    x[idx] = v;
    xh[idx] = __float2half_rn(v);
}

// ---------------- fused residual + LayerNorm --------------------------------
__global__ void __launch_bounds__(256) ln_res_kernel(
    const float* __restrict__ X, const float* __restrict__ Y,
    const float* __restrict__ g, const float* __restrict__ beta,
    float* __restrict__ out, __half* __restrict__ outh)
{
    __shared__ float sh[8];
    size_t base = (size_t)blockIdx.x * DD;
    int tid = threadIdx.x;
    int c = tid << 2;
    float4 xv = *(const float4*)(X + base + c);
    float4 yv = *(const float4*)(Y + base + c);
    float v[4] = {xv.x + yv.x, xv.y + yv.y, xv.z + yv.z, xv.w + yv.w};
    float s = v[0] + v[1] + v[2] + v[3];
#pragma unroll
    for (int o = 16; o; o >>= 1) s += __shfl_xor_sync(~0u, s, o);
    if ((tid & 31) == 0) sh[tid >> 5] = s;
    __syncthreads();
    s = sh[tid & 7];
#pragma unroll
    for (int o = 4; o; o >>= 1) s += __shfl_xor_sync(~0u, s, o);
    float mean = s * (1.f / DD);

    float q = 0.f;
#pragma unroll
    for (int j = 0; j < 4; j++){ float d = v[j] - mean; q += d * d; }
#pragma unroll
    for (int o = 16; o; o >>= 1) q += __shfl_xor_sync(~0u, q, o);
    __syncthreads();
    if ((tid & 31) == 0) sh[tid >> 5] = q;
    __syncthreads();
    q = sh[tid & 7];
#pragma unroll
    for (int o = 4; o; o >>= 1) q += __shfl_xor_sync(~0u, q, o);
    float rstd = rsqrtf(q * (1.f / DD) + 1e-6f);

    float4 gv = *(const float4*)(g + c);
    float4 bv = *(const float4*)(beta + c);
    float o0 = (v[0] - mean) * rstd * gv.x + bv.x;
    float o1 = (v[1] - mean) * rstd * gv.y + bv.y;
    float o2 = (v[2] - mean) * rstd * gv.z + bv.z;
    float o3 = (v[3] - mean) * rstd * gv.w + bv.w;
    float4 ov = {o0, o1, o2, o3};
    *(float4*)(out + base + c) = ov;
    uint2 hv = {packh2(o0, o1), packh2(o2, o3)};
    *(uint2*)(outh + base + c) = hv;
}

// ---------------- host launcher --------------------------------------------
extern "C" void kernel_launch(void* const* d_in, const int* in_sizes, int n_in,
                              void* d_out, int out_size)
{
    const int*   tokens = (const int*)  d_in[0];
    const float* mask   = (const float*)d_in[1];
    const float* emb    = (const float*)d_in[2];
    const float* Wq = (const float*)d_in[3];
    const float* bq = (const float*)d_in[4];
    const float* Wk = (const float*)d_in[5];
    const float* bk = (const float*)d_in[6];
    const float* Wv = (const float*)d_in[7];
    const float* bv = (const float*)d_in[8];
    const float* Wo = (const float*)d_in[9];
    const float* bo = (const float*)d_in[10];
    const float* W1 = (const float*)d_in[11];
    const float* b1 = (const float*)d_in[12];
    const float* W2 = (const float*)d_in[13];
    const float* b2 = (const float*)d_in[14];
    const float* g1 = (const float*)d_in[15];
    const float* be1 = (const float*)d_in[16];
    const float* g2 = (const float*)d_in[17];
    const float* be2 = (const float*)d_in[18];
    float* out = (float*)d_out;

    float *x, *tmp, *out1, *bqkv;
    __half *xh, *o1h, *ctxh, *qkvh, *hidh, *wqkv, *wot, *w1t, *w2t;
    cudaGetSymbolAddress((void**)&x,    g_x);
    cudaGetSymbolAddress((void**)&tmp,  g_tmp);
    cudaGetSymbolAddress((void**)&out1, g_out1);
    cudaGetSymbolAddress((void**)&xh,   g_xh);
    cudaGetSymbolAddress((void**)&o1h,  g_o1h);
    cudaGetSymbolAddress((void**)&ctxh, g_ctxh);
    cudaGetSymbolAddress((void**)&qkvh, g_qkvh);
    cudaGetSymbolAddress((void**)&hidh, g_hidh);
    cudaGetSymbolAddress((void**)&wqkv, g_wqkv);
    cudaGetSymbolAddress((void**)&wot,  g_wot);
    cudaGetSymbolAddress((void**)&w1t,  g_w1t);
    cudaGetSymbolAddress((void**)&w2t,  g_w2t);
    cudaGetSymbolAddress((void**)&bqkv, g_bqkv);

    cudaFuncSetAttribute(h_gemm<false,false,true>,
                         cudaFuncAttributeMaxDynamicSharedMemorySize, GSMEM);
    cudaFuncSetAttribute(h_gemm<false,true,false>,
                         cudaFuncAttributeMaxDynamicSharedMemorySize, GSMEM);
    cudaFuncSetAttribute(h_gemm<true,false,true>,
                         cudaFuncAttributeMaxDynamicSharedMemorySize, GSMEM);
    cudaFuncSetAttribute(flash_attn,
                         cudaFuncAttributeMaxDynamicSharedMemorySize, FL_SMEM);

    dim3 tb(32, 8);
    dim3 gQKV(3*DD / 256, MROWS / 128);
    dim3 gDD (DD / 256,  MROWS / 128);
    dim3 gFF (DFF / 256, MROWS / 128);
    dim3 gFL (SS / 128, BB * HH);

    // launch order: QKV GEMM is the 4th kernel launch (ncu samples #4)
    trans_qkv_kernel<<<dim3(32, 32, 3*LLAY), tb>>>(Wq, Wk, Wv, wqkv);   // 1
    bias_merge_kernel<<<(LLAY*3*DD)/256, 256>>>(bq, bk, bv, bqkv);      // 2
    embed_kernel<<<(MROWS * DD) / 256, 256>>>(tokens, emb, x, xh);      // 3
    h_gemm<false,false,true><<<gQKV, 512, GSMEM>>>(                     // 4
        xh, wqkv, bqkv, 0, qkvh, 3*DD, DD);
    trans_wo_kernel<<<dim3(32, 32, LLAY), tb>>>(Wo, wot);               // 5
    trans_w12_kernel<<<dim3(128, 32, 2*LLAY), tb>>>(W1, W2, w1t, w2t);  // 6

    for (int i = 0; i < LLAY; i++){
        size_t woq = (size_t)i * 3 * DD * DD;
        size_t wo2 = (size_t)i * DD * DD;
        size_t f1 = (size_t)i * DFF * DD;
        size_t f2 = (size_t)i * DD * DFF;

        if (i > 0)
            h_gemm<false,false,true><<<gQKV, 512, GSMEM>>>(
                xh, wqkv + woq, bqkv + i*3*DD, 0, qkvh, 3*DD, DD);

        flash_attn<<<gFL, 256, FL_SMEM>>>(qkvh, mask, ctxh);

        h_gemm<false,true,false><<<gDD, 512, GSMEM>>>(
            ctxh, wot + wo2, bo + i*DD, tmp, 0, DD, DD);
        ln_res_kernel<<<MROWS, 256>>>(x, tmp, g1 + i*DD, be1 + i*DD,
                                      out1, o1h);

        h_gemm<true,false,true><<<gFF, 512, GSMEM>>>(
            o1h, w1t + f1, b1 + i*DFF, 0, hidh, DFF, DD);
        h_gemm<false,true,false><<<gDD, 512, GSMEM>>>(
            hidh, w2t + f2, b2 + i*DD, tmp, 0, DD, DFF);

        float* dst = (i == LLAY - 1) ? out : x;
        ln_res_kernel<<<MROWS, 256>>>(out1, tmp, g2 + i*DD, be2 + i*DD,
                                      dst, xh);
    }
}